// round 6
// baseline (speedup 1.0000x reference)
#include <cuda_runtime.h>
#include <cstdint>

#define N_REFLNS 2000000
#define N_IMAGES 8192
#define N_RAC    1000000
#define MC       8
#define D_META   16
#define HIDDEN   32
#define LOG_2PI_F 1.8378770664093453f

// ---------------- scratch (static device globals; no allocation) ----------------
__device__ float4 g_zT[N_RAC * 2];       // z transposed: (N_RAC, 8) as 2x float4 per row
__device__ float  g_img_sum[N_IMAGES];
__device__ float  g_img_cnt[N_IMAGES];
__device__ float  g_kl_sum;
__device__ float  g_ll_total;
__device__ unsigned g_done;

// ---------------- tf32 helpers ----------------
__device__ __forceinline__ unsigned cvt_tf32(float x) {
    unsigned r;
    asm("cvt.rna.tf32.f32 %0, %1;" : "=r"(r) : "f"(x));
    return r;
}
// 2-term split: x ~= hi + lo, both tf32-representable (3xtf32 scheme)
__device__ __forceinline__ void split2(float x, unsigned& h, unsigned& l) {
    h = cvt_tf32(x);
    l = cvt_tf32(x - __uint_as_float(h));
}

// m16n8k8 tf32 MMA, D/C fp32 in-place accumulate
__device__ __forceinline__ void mma8(float4& d,
                                     unsigned a0, unsigned a1, unsigned a2, unsigned a3,
                                     unsigned b0, unsigned b1) {
    asm("mma.sync.aligned.m16n8k8.row.col.f32.tf32.tf32.f32 "
        "{%0,%1,%2,%3}, {%4,%5,%6,%7}, {%8,%9}, {%0,%1,%2,%3};"
        : "+f"(d.x), "+f"(d.y), "+f"(d.z), "+f"(d.w)
        : "r"(a0), "r"(a1), "r"(a2), "r"(a3), "r"(b0), "r"(b1));
}

__device__ __forceinline__ float softplus_f(float x) {
    float ax = fabsf(x);
    float t  = __expf(-ax);
    float l  = (t > 0.0078125f) ? __logf(1.0f + t) : fmaf(-0.5f * t, t, t);
    return fmaxf(x, 0.0f) + l;
}

// ---------------- kernel 0: zero accumulators ----------------
__global__ void init_kernel() {
    int i = blockIdx.x * blockDim.x + threadIdx.x;
    if (i < N_IMAGES) { g_img_sum[i] = 0.0f; g_img_cnt[i] = 0.0f; }
    if (i == 0) { g_kl_sum = 0.0f; g_ll_total = 0.0f; g_done = 0u; }
}

// ---------------- kernel 1: z transpose + KL reduction ----------------
__global__ __launch_bounds__(256) void zkl_kernel(const float* __restrict__ q_loc,
                                                  const float* __restrict__ q_ls,
                                                  const float* __restrict__ eps) {
    int m = blockIdx.x * 256 + threadIdx.x;
    float kl = 0.0f;
    if (m < N_RAC) {
        float loc = q_loc[m];
        float ls  = q_ls[m];
        float s   = __expf(ls);
        kl = fmaf(0.5f, fmaf(s, s, fmaf(loc, loc, -1.0f)), -ls);
        float z[8];
#pragma unroll
        for (int c = 0; c < 8; c++)
            z[c] = fmaf(s, eps[(size_t)c * N_RAC + m], loc);
        g_zT[2 * m]     = make_float4(z[0], z[1], z[2], z[3]);
        g_zT[2 * m + 1] = make_float4(z[4], z[5], z[6], z[7]);
    }
#pragma unroll
    for (int off = 16; off; off >>= 1)
        kl += __shfl_down_sync(0xffffffffu, kl, off);
    __shared__ float wsum[8];
    int lane = threadIdx.x & 31, wid = threadIdx.x >> 5;
    if (lane == 0) wsum[wid] = kl;
    __syncthreads();
    if (threadIdx.x == 0) {
        float t = 0.0f;
#pragma unroll
        for (int i = 0; i < 8; i++) t += wsum[i];
        atomicAdd(&g_kl_sum, t);
    }
}

// segmented warp reduce + atomic (image_id sorted -> contiguous segments)
__device__ __forceinline__ void seg_atomic(float ll, int img, int lane) {
    unsigned mask = __match_any_sync(0xffffffffu, img);
    int hi = 31 - __clz(mask);
    float v = ll;
#pragma unroll
    for (int off = 1; off < 32; off <<= 1) {
        float o = __shfl_down_sync(0xffffffffu, v, off);
        if (lane + off <= hi) v += o;
    }
    if (lane == (__ffs(mask) - 1)) {
        atomicAdd(&g_img_sum[img], v);
        atomicAdd(&g_img_cnt[img], (float)__popc(mask));
    }
}

// ---------------- kernel 2: tensor-core MLP + likelihood -------------------------
// Each warp processes chunks of 32 reflections: two m16 subtiles through
// layer1 (16x32, K=16) and layer2 (16x8, K=32) via 3xtf32 mma.sync.
#define HB_STRIDE 36   // conflict-free LDS (4q+tig distinct banks), 8B-aligned pairs
#define PB_STRIDE 12   // 16B-aligned float4 epilogue reads

__global__ __launch_bounds__(128) void refl_kernel(const float* __restrict__ metadata,
                                                   const float* __restrict__ W1,
                                                   const float* __restrict__ b1,
                                                   const float* __restrict__ W2,
                                                   const float* __restrict__ b2,
                                                   const float* __restrict__ iobs,
                                                   const float* __restrict__ sigiobs,
                                                   const int*   __restrict__ image_id,
                                                   const int*   __restrict__ miller_id,
                                                   float*       __restrict__ out) {
    __shared__ __align__(16) float h_buf[4][16 * HB_STRIDE];
    __shared__ __align__(16) float p_buf[4][32 * PB_STRIDE];

    int tid  = threadIdx.x;
    int w    = tid >> 5;
    int lane = tid & 31;
    int q    = lane >> 2;   // groupID (row within m16)
    int tig  = lane & 3;    // thread-in-group (k / col selector)
    float* hb = h_buf[w];
    float* pb = p_buf[w];

    // ---- per-thread weight fragments (hi/lo tf32 split), loaded once ----
    unsigned w1h[2][4][2], w1l[2][4][2];          // [k-step][n-tile][b0/b1]
#pragma unroll
    for (int s = 0; s < 2; s++)
#pragma unroll
        for (int j = 0; j < 4; j++) {
            float v0 = W1[(tig + 8 * s) * HIDDEN + 8 * j + q];
            float v1 = W1[(tig + 4 + 8 * s) * HIDDEN + 8 * j + q];
            split2(v0, w1h[s][j][0], w1l[s][j][0]);
            split2(v1, w1h[s][j][1], w1l[s][j][1]);
        }
    unsigned w2h[4][2], w2l[4][2];                 // [k-step][b0/b1]
#pragma unroll
    for (int s = 0; s < 4; s++) {
        float v0 = W2[(tig + 8 * s) * MC + q];
        float v1 = W2[(tig + 4 + 8 * s) * MC + q];
        split2(v0, w2h[s][0], w2l[s][0]);
        split2(v1, w2h[s][1], w2l[s][1]);
    }
    float bias1x[4], bias1y[4];
#pragma unroll
    for (int j = 0; j < 4; j++) {
        bias1x[j] = b1[8 * j + 2 * tig];
        bias1y[j] = b1[8 * j + 2 * tig + 1];
    }
    float b2x = b2[2 * tig], b2y = b2[2 * tig + 1];

    const int nchunks = N_REFLNS / 32;             // 62500, exact
    int gwarp  = blockIdx.x * 4 + w;
    int nwarps = gridDim.x * 4;

    for (int chunk = gwarp; chunk < nchunks; chunk += nwarps) {
        int base = chunk * 32;

#pragma unroll
        for (int t = 0; t < 2; t++) {
            int r0 = base + 16 * t;
            const float* Ma = metadata + (size_t)(r0 + q) * D_META;
            const float* Mb = metadata + (size_t)(r0 + q + 8) * D_META;

            // ---- layer1 A fragments (meta), hi/lo split ----
            unsigned ah[2][4], al[2][4];
#pragma unroll
            for (int s = 0; s < 2; s++) {
                split2(Ma[tig + 8 * s],     ah[s][0], al[s][0]);
                split2(Mb[tig + 8 * s],     ah[s][1], al[s][1]);
                split2(Ma[tig + 4 + 8 * s], ah[s][2], al[s][2]);
                split2(Mb[tig + 4 + 8 * s], ah[s][3], al[s][3]);
            }

            // ---- layer1: h = meta @ W1 + b1 (bias folded into C init) ----
            float4 acc[4];
#pragma unroll
            for (int j = 0; j < 4; j++)
                acc[j] = make_float4(bias1x[j], bias1y[j], bias1x[j], bias1y[j]);
#pragma unroll
            for (int s = 0; s < 2; s++)
#pragma unroll
                for (int j = 0; j < 4; j++) {
                    mma8(acc[j], ah[s][0], ah[s][1], ah[s][2], ah[s][3], w1h[s][j][0], w1h[s][j][1]);
                    mma8(acc[j], al[s][0], al[s][1], al[s][2], al[s][3], w1h[s][j][0], w1h[s][j][1]);
                    mma8(acc[j], ah[s][0], ah[s][1], ah[s][2], ah[s][3], w1l[s][j][0], w1l[s][j][1]);
                }

            // ---- relu, stage h in SMEM [16][HB_STRIDE] ----
#pragma unroll
            for (int j = 0; j < 4; j++) {
                float2 lo = make_float2(fmaxf(acc[j].x, 0.0f), fmaxf(acc[j].y, 0.0f));
                float2 hi = make_float2(fmaxf(acc[j].z, 0.0f), fmaxf(acc[j].w, 0.0f));
                *(float2*)&hb[q * HB_STRIDE + 8 * j + 2 * tig]       = lo;
                *(float2*)&hb[(q + 8) * HB_STRIDE + 8 * j + 2 * tig] = hi;
            }
            __syncwarp();

            // ---- layer2 A fragments from SMEM h ----
            unsigned a2h[4][4], a2l[4][4];
#pragma unroll
            for (int s = 0; s < 4; s++) {
                split2(hb[q * HB_STRIDE + tig + 8 * s],           a2h[s][0], a2l[s][0]);
                split2(hb[(q + 8) * HB_STRIDE + tig + 8 * s],     a2h[s][1], a2l[s][1]);
                split2(hb[q * HB_STRIDE + tig + 4 + 8 * s],       a2h[s][2], a2l[s][2]);
                split2(hb[(q + 8) * HB_STRIDE + tig + 4 + 8 * s], a2h[s][3], a2l[s][3]);
            }

            // ---- layer2: p = relu(h) @ W2 + b2 ----
            float4 p = make_float4(b2x, b2y, b2x, b2y);
#pragma unroll
            for (int s = 0; s < 4; s++) {
                mma8(p, a2h[s][0], a2h[s][1], a2h[s][2], a2h[s][3], w2h[s][0], w2h[s][1]);
                mma8(p, a2l[s][0], a2l[s][1], a2l[s][2], a2l[s][3], w2h[s][0], w2h[s][1]);
                mma8(p, a2h[s][0], a2h[s][1], a2h[s][2], a2h[s][3], w2l[s][0], w2l[s][1]);
            }

            *(float2*)&pb[(16 * t + q) * PB_STRIDE + 2 * tig]     = make_float2(p.x, p.y);
            *(float2*)&pb[(16 * t + q + 8) * PB_STRIDE + 2 * tig] = make_float2(p.z, p.w);
            __syncwarp();   // hb reuse next subtile / pb complete before epilogue
        }

        // ---- epilogue: 1 reflection per lane ----
        int r = base + lane;
        float4 pa = *(float4*)&pb[lane * PB_STRIDE];
        float4 pc = *(float4*)&pb[lane * PB_STRIDE + 4];
        float pv[8] = {pa.x, pa.y, pa.z, pa.w, pc.x, pc.y, pc.z, pc.w};
        float scale[8];
#pragma unroll
        for (int c = 0; c < 8; c++) scale[c] = softplus_f(pv[c]);

        int mid = miller_id[r];
        float4 f0 = g_zT[2 * mid];
        float4 f1 = g_zT[2 * mid + 1];
        float f[8] = {f0.x, f0.y, f0.z, f0.w, f1.x, f1.y, f1.z, f1.w};

        float io  = iobs[r];
        float sg  = sigiobs[r];
        float inv = 1.0f / sg;

        float sum_i = 0.0f, ss = 0.0f;
#pragma unroll
        for (int c = 0; c < 8; c++) {
            float ip = f[c] * f[c] * scale[c];
            sum_i += ip;
            float rr = (ip - io) * inv;
            ss = fmaf(rr, rr, ss);
        }
        out[r] = sum_i * 0.125f;
        float ll = fmaf(-0.5f, ss, -8.0f * (__logf(sg) + 0.5f * LOG_2PI_F));
        seg_atomic(ll, image_id[r], lane);
        __syncwarp();   // pb safe to overwrite next chunk
    }
}

// ---------------- kernel 3: parallel finalize (8 blocks, last block writes) -----
__global__ __launch_bounds__(1024) void finalize_kernel(float* __restrict__ out) {
    int i = blockIdx.x * 1024 + threadIdx.x;
    float v = g_img_sum[i] * (1.0f / fmaxf(g_img_cnt[i], 1.0f));
#pragma unroll
    for (int off = 16; off; off >>= 1)
        v += __shfl_down_sync(0xffffffffu, v, off);
    __shared__ float wsum[32];
    int lane = threadIdx.x & 31, wid = threadIdx.x >> 5;
    if (lane == 0) wsum[wid] = v;
    __syncthreads();
    if (wid == 0) {
        float t = wsum[lane];
#pragma unroll
        for (int off = 16; off; off >>= 1)
            t += __shfl_down_sync(0xffffffffu, t, off);
        if (lane == 0) {
            atomicAdd(&g_ll_total, t);
            __threadfence();
            unsigned ticket = atomicAdd(&g_done, 1u);
            if (ticket == gridDim.x - 1) {
                float total = atomicAdd(&g_ll_total, 0.0f);  // fenced read of final sum
                out[N_REFLNS]     = -(total / (float)MC) / (float)N_IMAGES;
                out[N_REFLNS + 1] = g_kl_sum * (1.0f / (float)N_RAC);
            }
        }
    }
}

// ---------------- launch ----------------
extern "C" void kernel_launch(void* const* d_in, const int* in_sizes, int n_in,
                              void* d_out, int out_size) {
    const float* q_loc     = (const float*)d_in[0];
    const float* q_ls      = (const float*)d_in[1];
    const float* eps       = (const float*)d_in[2];
    const float* metadata  = (const float*)d_in[3];
    const float* W1        = (const float*)d_in[4];
    const float* b1        = (const float*)d_in[5];
    const float* W2        = (const float*)d_in[6];
    const float* b2        = (const float*)d_in[7];
    const float* iobs      = (const float*)d_in[8];
    const float* sigiobs   = (const float*)d_in[9];
    const int*   image_id  = (const int*)d_in[10];
    const int*   miller_id = (const int*)d_in[11];
    float* out = (float*)d_out;

    init_kernel<<<(N_IMAGES + 255) / 256, 256>>>();
    zkl_kernel<<<(N_RAC + 255) / 256, 256>>>(q_loc, q_ls, eps);
    refl_kernel<<<2048, 128>>>(metadata, W1, b1, W2, b2,
                               iobs, sigiobs, image_id, miller_id, out);
    finalize_kernel<<<N_IMAGES / 1024, 1024>>>(out);
}

// round 7
// speedup vs baseline: 1.1610x; 1.1610x over previous
#include <cuda_runtime.h>
#include <cuda_fp16.h>
#include <cstdint>

#define N_REFLNS 2000000
#define N_IMAGES 8192
#define N_RAC    1000000
#define MC       8
#define D_META   16
#define HIDDEN   32
#define LOG_2PI_F 1.8378770664093453f

// ---------------- scratch (static device globals; no allocation) ----------------
__device__ float4 g_zT[N_RAC * 2];       // z transposed: (N_RAC, 8)
__device__ float  g_img_sum[N_IMAGES];
__device__ float  g_img_cnt[N_IMAGES];
__device__ float  g_kl_sum;
__device__ float  g_ll_total;
__device__ unsigned g_done;

// ---------------- helpers ----------------
// fp16 hi/lo split of an f32 pair -> two f16x2 regs (x in low half)
__device__ __forceinline__ void split_pair(float x, float y, unsigned& hi, unsigned& lo) {
    __half2 h = __floats2half2_rn(x, y);
    float2 hf = __half22float2(h);
    __half2 l = __floats2half2_rn(x - hf.x, y - hf.y);
    hi = *reinterpret_cast<unsigned*>(&h);
    lo = *reinterpret_cast<unsigned*>(&l);
}

// m16n8k16 f16 MMA, f32 accumulate in place
__device__ __forceinline__ void mma16(float4& d,
                                      unsigned a0, unsigned a1, unsigned a2, unsigned a3,
                                      unsigned b0, unsigned b1) {
    asm("mma.sync.aligned.m16n8k16.row.col.f32.f16.f16.f32 "
        "{%0,%1,%2,%3}, {%4,%5,%6,%7}, {%8,%9}, {%0,%1,%2,%3};"
        : "+f"(d.x), "+f"(d.y), "+f"(d.z), "+f"(d.w)
        : "r"(a0), "r"(a1), "r"(a2), "r"(a3), "r"(b0), "r"(b1));
}

__device__ __forceinline__ float softplus_f(float x) {
    float ax = fabsf(x);
    float t  = __expf(-ax);
    float l  = (t > 0.0078125f) ? __logf(1.0f + t) : fmaf(-0.5f * t, t, t);
    return fmaxf(x, 0.0f) + l;
}

// ---------------- kernel 1: init + z transpose + KL ----------------
__global__ __launch_bounds__(256) void zkl_kernel(const float* __restrict__ q_loc,
                                                  const float* __restrict__ q_ls,
                                                  const float* __restrict__ eps) {
    int m = blockIdx.x * 256 + threadIdx.x;
    if (m < N_IMAGES) { g_img_sum[m] = 0.0f; g_img_cnt[m] = 0.0f; }
    if (m == 0) { g_kl_sum = 0.0f; g_ll_total = 0.0f; g_done = 0u; }
    float kl = 0.0f;
    if (m < N_RAC) {
        float loc = q_loc[m];
        float ls  = q_ls[m];
        float s   = __expf(ls);
        kl = fmaf(0.5f, fmaf(s, s, fmaf(loc, loc, -1.0f)), -ls);
        float z[8];
#pragma unroll
        for (int c = 0; c < 8; c++)
            z[c] = fmaf(s, eps[(size_t)c * N_RAC + m], loc);
        g_zT[2 * m]     = make_float4(z[0], z[1], z[2], z[3]);
        g_zT[2 * m + 1] = make_float4(z[4], z[5], z[6], z[7]);
    }
#pragma unroll
    for (int off = 16; off; off >>= 1)
        kl += __shfl_down_sync(0xffffffffu, kl, off);
    __shared__ float wsum[8];
    int lane = threadIdx.x & 31, wid = threadIdx.x >> 5;
    if (lane == 0) wsum[wid] = kl;
    __syncthreads();
    if (threadIdx.x == 0) {
        float t = 0.0f;
#pragma unroll
        for (int i = 0; i < 8; i++) t += wsum[i];
        atomicAdd(&g_kl_sum, t);
    }
}

// generalized segmented warp reduce + atomic; lanes with img<0 carry v=0
__device__ __forceinline__ void seg_atomic(float v, int img, int lane) {
    unsigned mask = __match_any_sync(0xffffffffu, img);
    int hi = 31 - __clz(mask);
#pragma unroll
    for (int off = 1; off < 32; off <<= 1) {
        float o = __shfl_down_sync(0xffffffffu, v, off);
        if (lane + off <= hi) v += o;
    }
    if (img >= 0 && lane == (__ffs(mask) - 1)) {
        atomicAdd(&g_img_sum[img], v);
        atomicAdd(&g_img_cnt[img], (float)__popc(mask));
    }
}

// ---------------- kernel 2: fp16x3 tensor MLP + likelihood ----------------------
// Warp handles chunks of 32 reflections (two m16 subtiles). Layer1 (K=16) and
// layer2 (K=32, 2 k-steps) as m16n8k16 fp16 MMAs with hi/lo 3-term compensation.
// C-fragment of layer1 feeds A-fragment of layer2 directly in registers.
__global__ __launch_bounds__(128) void refl_kernel(const float* __restrict__ metadata,
                                                   const float* __restrict__ W1,
                                                   const float* __restrict__ b1,
                                                   const float* __restrict__ W2,
                                                   const float* __restrict__ b2,
                                                   const float* __restrict__ iobs,
                                                   const float* __restrict__ sigiobs,
                                                   const int*   __restrict__ image_id,
                                                   const int*   __restrict__ miller_id,
                                                   float*       __restrict__ out) {
    int tid  = threadIdx.x;
    int w    = tid >> 5;
    int lane = tid & 31;
    int q    = lane >> 2;   // groupID: row within m16
    int tig  = lane & 3;    // thread-in-group: k/col pair selector

    // ---- weight fragments (hi/lo fp16), loaded once per warp ----
    // layer1 B: n-tile j (hidden cols 8j..8j+7): b0=(k=2tig,2tig+1, n=q), b1=(k=2tig+8,+9, n=q)
    unsigned w1h[4][2], w1l[4][2];
#pragma unroll
    for (int j = 0; j < 4; j++) {
        int col = 8 * j + q;
        split_pair(W1[(2 * tig) * HIDDEN + col],     W1[(2 * tig + 1) * HIDDEN + col], w1h[j][0], w1l[j][0]);
        split_pair(W1[(2 * tig + 8) * HIDDEN + col], W1[(2 * tig + 9) * HIDDEN + col], w1h[j][1], w1l[j][1]);
    }
    // layer2 B: k-step s (hidden rows 16s..16s+15), n=q (MC col)
    unsigned w2h[2][2], w2l[2][2];
#pragma unroll
    for (int s = 0; s < 2; s++) {
        int k0 = 16 * s + 2 * tig;
        split_pair(W2[k0 * MC + q],       W2[(k0 + 1) * MC + q], w2h[s][0], w2l[s][0]);
        split_pair(W2[(k0 + 8) * MC + q], W2[(k0 + 9) * MC + q], w2h[s][1], w2l[s][1]);
    }
    float b1x[4], b1y[4];
#pragma unroll
    for (int j = 0; j < 4; j++) { b1x[j] = b1[8 * j + 2 * tig]; b1y[j] = b1[8 * j + 2 * tig + 1]; }
    float b2x = b2[2 * tig], b2y = b2[2 * tig + 1];

    const float* zTf = (const float*)g_zT;
    const int nchunks = N_REFLNS / 32;     // 62500 exact
    int gwarp  = blockIdx.x * 4 + w;
    int nwarps = gridDim.x * 4;

    for (int chunk = gwarp; chunk < nchunks; chunk += nwarps) {
        int base = chunk * 32;

#pragma unroll
        for (int t = 0; t < 2; t++) {
            int r0 = base + 16 * t;
            const float* Ma = metadata + (size_t)(r0 + q) * D_META;
            const float* Mb = metadata + (size_t)(r0 + q + 8) * D_META;

            // A-fragments: a0=(q, k=2tig,2tig+1) a1=(q+8,..) a2=(q, k=2tig+8,+9) a3=(q+8,..)
            float2 va0 = *(const float2*)(Ma + 2 * tig);
            float2 va1 = *(const float2*)(Mb + 2 * tig);
            float2 va2 = *(const float2*)(Ma + 2 * tig + 8);
            float2 va3 = *(const float2*)(Mb + 2 * tig + 8);
            unsigned ah[4], al[4];
            split_pair(va0.x, va0.y, ah[0], al[0]);
            split_pair(va1.x, va1.y, ah[1], al[1]);
            split_pair(va2.x, va2.y, ah[2], al[2]);
            split_pair(va3.x, va3.y, ah[3], al[3]);

            // ---- layer1: h = meta @ W1 + b1 (bias in C init), 3-term ----
            float4 acc[4];
#pragma unroll
            for (int j = 0; j < 4; j++) {
                acc[j] = make_float4(b1x[j], b1y[j], b1x[j], b1y[j]);
                mma16(acc[j], ah[0], ah[1], ah[2], ah[3], w1h[j][0], w1h[j][1]);
                mma16(acc[j], al[0], al[1], al[2], al[3], w1h[j][0], w1h[j][1]);
                mma16(acc[j], ah[0], ah[1], ah[2], ah[3], w1l[j][0], w1l[j][1]);
            }

            // ---- layer2: p = relu(h) @ W2 + b2; C-frag pairs ARE A-frag pairs ----
            float4 p = make_float4(b2x, b2y, b2x, b2y);
#pragma unroll
            for (int s = 0; s < 2; s++) {
                const float4& cA = acc[2 * s];       // hidden cols 16s+2tig,+1
                const float4& cB = acc[2 * s + 1];   // hidden cols 16s+8+2tig,+1
                unsigned a2h[4], a2l[4];
                split_pair(fmaxf(cA.x, 0.0f), fmaxf(cA.y, 0.0f), a2h[0], a2l[0]);
                split_pair(fmaxf(cA.z, 0.0f), fmaxf(cA.w, 0.0f), a2h[1], a2l[1]);
                split_pair(fmaxf(cB.x, 0.0f), fmaxf(cB.y, 0.0f), a2h[2], a2l[2]);
                split_pair(fmaxf(cB.z, 0.0f), fmaxf(cB.w, 0.0f), a2h[3], a2l[3]);
                mma16(p, a2h[0], a2h[1], a2h[2], a2h[3], w2h[s][0], w2h[s][1]);
                mma16(p, a2l[0], a2l[1], a2l[2], a2l[3], w2h[s][0], w2h[s][1]);
                mma16(p, a2h[0], a2h[1], a2h[2], a2h[3], w2l[s][0], w2l[s][1]);
            }
            // p: rows q (x,y), q+8 (z,w); cols 2tig, 2tig+1

            // ---- cooperative epilogue: 4 threads per reflection ----
            int rq  = r0 + q;
            int rq8 = rq + 8;
            float s0 = softplus_f(p.x), s1 = softplus_f(p.y);
            float s2 = softplus_f(p.z), s3 = softplus_f(p.w);

            int midq  = miller_id[rq];
            int midq8 = miller_id[rq8];
            float2 fq  = *(const float2*)(zTf + (size_t)midq * 8 + 2 * tig);
            float2 fq8 = *(const float2*)(zTf + (size_t)midq8 * 8 + 2 * tig);

            float ioq  = iobs[rq],  sgq  = sigiobs[rq],  invq  = 1.0f / sgq;
            float ioq8 = iobs[rq8], sgq8 = sigiobs[rq8], invq8 = 1.0f / sgq8;

            float ip0 = fq.x * fq.x * s0,   ip1 = fq.y * fq.y * s1;
            float ip2 = fq8.x * fq8.x * s2, ip3 = fq8.y * fq8.y * s3;
            float siq  = ip0 + ip1;
            float siq8 = ip2 + ip3;
            float r0q  = (ip0 - ioq) * invq,   r1q = (ip1 - ioq) * invq;
            float r0q8 = (ip2 - ioq8) * invq8, r1q8 = (ip3 - ioq8) * invq8;
            float ssq  = fmaf(r0q, r0q, r1q * r1q);
            float ssq8 = fmaf(r0q8, r0q8, r1q8 * r1q8);

            // reduce over the 4 tig lanes (xor 1, 2)
#pragma unroll
            for (int off = 1; off < 4; off <<= 1) {
                siq  += __shfl_xor_sync(0xffffffffu, siq,  off);
                ssq  += __shfl_xor_sync(0xffffffffu, ssq,  off);
                siq8 += __shfl_xor_sync(0xffffffffu, siq8, off);
                ssq8 += __shfl_xor_sync(0xffffffffu, ssq8, off);
            }

            float llq = 0.0f, llq8 = 0.0f;
            int imgq = -1, imgq8 = -1;
            if (tig == 0) {
                out[rq]  = siq  * 0.125f;
                out[rq8] = siq8 * 0.125f;
                llq  = fmaf(-0.5f, ssq,  -8.0f * (__logf(sgq)  + 0.5f * LOG_2PI_F));
                llq8 = fmaf(-0.5f, ssq8, -8.0f * (__logf(sgq8) + 0.5f * LOG_2PI_F));
                imgq  = image_id[rq];
                imgq8 = image_id[rq8];
            }
            seg_atomic(llq,  imgq,  lane);
            seg_atomic(llq8, imgq8, lane);
        }
    }
}

// ---------------- kernel 3: parallel finalize (8 blocks, last writes scalars) ---
__global__ __launch_bounds__(1024) void finalize_kernel(float* __restrict__ out) {
    int i = blockIdx.x * 1024 + threadIdx.x;
    float v = g_img_sum[i] * (1.0f / fmaxf(g_img_cnt[i], 1.0f));
#pragma unroll
    for (int off = 16; off; off >>= 1)
        v += __shfl_down_sync(0xffffffffu, v, off);
    __shared__ float wsum[32];
    int lane = threadIdx.x & 31, wid = threadIdx.x >> 5;
    if (lane == 0) wsum[wid] = v;
    __syncthreads();
    if (wid == 0) {
        float t = wsum[lane];
#pragma unroll
        for (int off = 16; off; off >>= 1)
            t += __shfl_down_sync(0xffffffffu, t, off);
        if (lane == 0) {
            atomicAdd(&g_ll_total, t);
            __threadfence();
            unsigned ticket = atomicAdd(&g_done, 1u);
            if (ticket == gridDim.x - 1) {
                float total = atomicAdd(&g_ll_total, 0.0f);
                out[N_REFLNS]     = -(total / (float)MC) / (float)N_IMAGES;
                out[N_REFLNS + 1] = g_kl_sum * (1.0f / (float)N_RAC);
            }
        }
    }
}

// ---------------- launch ----------------
extern "C" void kernel_launch(void* const* d_in, const int* in_sizes, int n_in,
                              void* d_out, int out_size) {
    const float* q_loc     = (const float*)d_in[0];
    const float* q_ls      = (const float*)d_in[1];
    const float* eps       = (const float*)d_in[2];
    const float* metadata  = (const float*)d_in[3];
    const float* W1        = (const float*)d_in[4];
    const float* b1        = (const float*)d_in[5];
    const float* W2        = (const float*)d_in[6];
    const float* b2        = (const float*)d_in[7];
    const float* iobs      = (const float*)d_in[8];
    const float* sigiobs   = (const float*)d_in[9];
    const int*   image_id  = (const int*)d_in[10];
    const int*   miller_id = (const int*)d_in[11];
    float* out = (float*)d_out;

    zkl_kernel<<<(N_RAC + 255) / 256, 256>>>(q_loc, q_ls, eps);
    refl_kernel<<<2368, 128>>>(metadata, W1, b1, W2, b2,
                               iobs, sigiobs, image_id, miller_id, out);
    finalize_kernel<<<N_IMAGES / 1024, 1024>>>(out);
}

// round 9
// speedup vs baseline: 1.4754x; 1.2709x over previous
#include <cuda_runtime.h>
#include <cuda_fp16.h>
#include <cstdint>

#define N_REFLNS 2000000
#define N_IMAGES 8192
#define N_RAC    1000000
#define MC       8
#define D_META   16
#define HIDDEN   32
#define LOG_2PI_F 1.8378770664093453f

// ---------------- scratch (static device globals; no allocation) ----------------
__device__ float4 g_zT[N_RAC * 2];       // z transposed: (N_RAC, 8)
__device__ float  g_img_sum[N_IMAGES];
__device__ float  g_img_cnt[N_IMAGES];
__device__ float  g_kl_sum;
__device__ float  g_ll_total;
__device__ unsigned g_done;

// ---------------- helpers ----------------
__device__ __forceinline__ void split_pair(float x, float y, unsigned& hi, unsigned& lo) {
    __half2 h = __floats2half2_rn(x, y);
    float2 hf = __half22float2(h);
    __half2 l = __floats2half2_rn(x - hf.x, y - hf.y);
    hi = *reinterpret_cast<unsigned*>(&h);
    lo = *reinterpret_cast<unsigned*>(&l);
}

__device__ __forceinline__ void mma16(float4& d,
                                      unsigned a0, unsigned a1, unsigned a2, unsigned a3,
                                      unsigned b0, unsigned b1) {
    asm("mma.sync.aligned.m16n8k16.row.col.f32.f16.f16.f32 "
        "{%0,%1,%2,%3}, {%4,%5,%6,%7}, {%8,%9}, {%0,%1,%2,%3};"
        : "+f"(d.x), "+f"(d.y), "+f"(d.z), "+f"(d.w)
        : "r"(a0), "r"(a1), "r"(a2), "r"(a3), "r"(b0), "r"(b1));
}

__device__ __forceinline__ float softplus_f(float x) {
    float ax = fabsf(x);
    float t  = __expf(-ax);
    float l  = (t > 0.0078125f) ? __logf(1.0f + t) : fmaf(-0.5f * t, t, t);
    return fmaxf(x, 0.0f) + l;
}

// ---------------- kernel 1: init + z transpose + KL ----------------
__global__ __launch_bounds__(256) void zkl_kernel(const float* __restrict__ q_loc,
                                                  const float* __restrict__ q_ls,
                                                  const float* __restrict__ eps) {
    int m = blockIdx.x * 256 + threadIdx.x;
    if (m < N_IMAGES) { g_img_sum[m] = 0.0f; g_img_cnt[m] = 0.0f; }
    if (m == 0) { g_kl_sum = 0.0f; g_ll_total = 0.0f; g_done = 0u; }
    float kl = 0.0f;
    if (m < N_RAC) {
        float loc = q_loc[m];
        float ls  = q_ls[m];
        float s   = __expf(ls);
        kl = fmaf(0.5f, fmaf(s, s, fmaf(loc, loc, -1.0f)), -ls);
        float z[8];
#pragma unroll
        for (int c = 0; c < 8; c++)
            z[c] = fmaf(s, __ldcs(eps + (size_t)c * N_RAC + m), loc);
        g_zT[2 * m]     = make_float4(z[0], z[1], z[2], z[3]);
        g_zT[2 * m + 1] = make_float4(z[4], z[5], z[6], z[7]);
    }
#pragma unroll
    for (int off = 16; off; off >>= 1)
        kl += __shfl_down_sync(0xffffffffu, kl, off);
    __shared__ float wsum[8];
    int lane = threadIdx.x & 31, wid = threadIdx.x >> 5;
    if (lane == 0) wsum[wid] = kl;
    __syncthreads();
    if (threadIdx.x == 0) {
        float t = 0.0f;
#pragma unroll
        for (int i = 0; i < 8; i++) t += wsum[i];
        atomicAdd(&g_kl_sum, t);
    }
}

// segmented warp reduce + atomic; lanes with img<0 carry v=0
// (popc(mask) of live img lanes == reflection count for that image — do NOT
//  pre-merge lanes, it corrupts the counts; learned in R7)
__device__ __forceinline__ void seg_atomic(float v, int img, int lane) {
    unsigned mask = __match_any_sync(0xffffffffu, img);
    int hi = 31 - __clz(mask);
#pragma unroll
    for (int off = 1; off < 32; off <<= 1) {
        float o = __shfl_down_sync(0xffffffffu, v, off);
        if (lane + off <= hi) v += o;
    }
    if (img >= 0 && lane == (__ffs(mask) - 1)) {
        atomicAdd(&g_img_sum[img], v);
        atomicAdd(&g_img_cnt[img], (float)__popc(mask));
    }
}

// ---------------- kernel 2: fp16x3 tensor MLP + likelihood, load-hoisted --------
__global__ __launch_bounds__(128, 4) void refl_kernel(const float* __restrict__ metadata,
                                                      const float* __restrict__ W1,
                                                      const float* __restrict__ b1,
                                                      const float* __restrict__ W2,
                                                      const float* __restrict__ b2,
                                                      const float* __restrict__ iobs,
                                                      const float* __restrict__ sigiobs,
                                                      const int*   __restrict__ image_id,
                                                      const int*   __restrict__ miller_id,
                                                      float*       __restrict__ out) {
    int tid  = threadIdx.x;
    int w    = tid >> 5;
    int lane = tid & 31;
    int q    = lane >> 2;   // groupID: row within m16
    int tig  = lane & 3;    // thread-in-group: k/col pair selector

    // ---- weight fragments (hi/lo fp16), loaded once per warp ----
    unsigned w1h[4][2], w1l[4][2];
#pragma unroll
    for (int j = 0; j < 4; j++) {
        int col = 8 * j + q;
        split_pair(W1[(2 * tig) * HIDDEN + col],     W1[(2 * tig + 1) * HIDDEN + col], w1h[j][0], w1l[j][0]);
        split_pair(W1[(2 * tig + 8) * HIDDEN + col], W1[(2 * tig + 9) * HIDDEN + col], w1h[j][1], w1l[j][1]);
    }
    unsigned w2h[2][2], w2l[2][2];
#pragma unroll
    for (int s = 0; s < 2; s++) {
        int k0 = 16 * s + 2 * tig;
        split_pair(W2[k0 * MC + q],       W2[(k0 + 1) * MC + q], w2h[s][0], w2l[s][0]);
        split_pair(W2[(k0 + 8) * MC + q], W2[(k0 + 9) * MC + q], w2h[s][1], w2l[s][1]);
    }
    float b1x[4], b1y[4];
#pragma unroll
    for (int j = 0; j < 4; j++) { b1x[j] = b1[8 * j + 2 * tig]; b1y[j] = b1[8 * j + 2 * tig + 1]; }
    float b2x = b2[2 * tig], b2y = b2[2 * tig + 1];

    const float* zTf = (const float*)g_zT;
    const int nchunks = N_REFLNS / 32;     // 62500 exact
    int gwarp  = blockIdx.x * 4 + w;
    int nwarps = gridDim.x * 4;

    for (int chunk = gwarp; chunk < nchunks; chunk += nwarps) {
        int base = chunk * 32;
        int r[4] = {base + q, base + q + 8, base + 16 + q, base + 24 + q};

        // ======== PHASE 1: issue ALL independent loads back-to-back ========
        float2 va[2][4];
#pragma unroll
        for (int t = 0; t < 2; t++) {
            const float* Ma = metadata + (size_t)r[2 * t] * D_META;
            const float* Mb = metadata + (size_t)r[2 * t + 1] * D_META;
            va[t][0] = __ldcs((const float2*)(Ma + 2 * tig));
            va[t][1] = __ldcs((const float2*)(Mb + 2 * tig));
            va[t][2] = __ldcs((const float2*)(Ma + 2 * tig + 8));
            va[t][3] = __ldcs((const float2*)(Mb + 2 * tig + 8));
        }
        int   mid[4], img[4];
        float io[4], sg[4];
#pragma unroll
        for (int i = 0; i < 4; i++) mid[i] = __ldcs(miller_id + r[i]);
#pragma unroll
        for (int i = 0; i < 4; i++) { io[i] = __ldcs(iobs + r[i]); sg[i] = __ldcs(sigiobs + r[i]); }
#pragma unroll
        for (int i = 0; i < 4; i++) img[i] = __ldcs(image_id + r[i]);
        // zT gather issued BEFORE the MLP — overlaps all MMA work
        float2 fv[4];
#pragma unroll
        for (int i = 0; i < 4; i++)
            fv[i] = *(const float2*)(zTf + (size_t)mid[i] * 8 + 2 * tig);

        // ======== PHASE 2: compute both subtiles ========
        float llv[4]; int imgv[4];
#pragma unroll
        for (int t = 0; t < 2; t++) {
            unsigned ah[4], al[4];
            split_pair(va[t][0].x, va[t][0].y, ah[0], al[0]);
            split_pair(va[t][1].x, va[t][1].y, ah[1], al[1]);
            split_pair(va[t][2].x, va[t][2].y, ah[2], al[2]);
            split_pair(va[t][3].x, va[t][3].y, ah[3], al[3]);

            // layer1: h = meta @ W1 + b1 (bias in C init), 3-term fp16
            float4 acc[4];
#pragma unroll
            for (int j = 0; j < 4; j++) {
                acc[j] = make_float4(b1x[j], b1y[j], b1x[j], b1y[j]);
                mma16(acc[j], ah[0], ah[1], ah[2], ah[3], w1h[j][0], w1h[j][1]);
                mma16(acc[j], al[0], al[1], al[2], al[3], w1h[j][0], w1h[j][1]);
                mma16(acc[j], ah[0], ah[1], ah[2], ah[3], w1l[j][0], w1l[j][1]);
            }

            // layer2: p = relu(h) @ W2 + b2; C-frag pairs feed A-frags directly
            float4 p = make_float4(b2x, b2y, b2x, b2y);
#pragma unroll
            for (int s = 0; s < 2; s++) {
                const float4& cA = acc[2 * s];
                const float4& cB = acc[2 * s + 1];
                unsigned a2h[4], a2l[4];
                split_pair(fmaxf(cA.x, 0.0f), fmaxf(cA.y, 0.0f), a2h[0], a2l[0]);
                split_pair(fmaxf(cA.z, 0.0f), fmaxf(cA.w, 0.0f), a2h[1], a2l[1]);
                split_pair(fmaxf(cB.x, 0.0f), fmaxf(cB.y, 0.0f), a2h[2], a2l[2]);
                split_pair(fmaxf(cB.z, 0.0f), fmaxf(cB.w, 0.0f), a2h[3], a2l[3]);
                mma16(p, a2h[0], a2h[1], a2h[2], a2h[3], w2h[s][0], w2h[s][1]);
                mma16(p, a2l[0], a2l[1], a2l[2], a2l[3], w2h[s][0], w2h[s][1]);
                mma16(p, a2h[0], a2h[1], a2h[2], a2h[3], w2l[s][0], w2l[s][1]);
            }
            // p: rows q (x,y) / q+8 (z,w); cols 2tig, 2tig+1

            // cooperative epilogue: 4 tig lanes per reflection
            int iq = 2 * t, iq8 = 2 * t + 1;
            float s0 = softplus_f(p.x), s1 = softplus_f(p.y);
            float s2 = softplus_f(p.z), s3 = softplus_f(p.w);

            float invq  = 1.0f / sg[iq];
            float invq8 = 1.0f / sg[iq8];

            float ip0 = fv[iq].x  * fv[iq].x  * s0, ip1 = fv[iq].y  * fv[iq].y  * s1;
            float ip2 = fv[iq8].x * fv[iq8].x * s2, ip3 = fv[iq8].y * fv[iq8].y * s3;
            float siq  = ip0 + ip1;
            float siq8 = ip2 + ip3;
            float r0q  = (ip0 - io[iq])  * invq,  r1q  = (ip1 - io[iq])  * invq;
            float r0q8 = (ip2 - io[iq8]) * invq8, r1q8 = (ip3 - io[iq8]) * invq8;
            float ssq  = fmaf(r0q,  r0q,  r1q  * r1q);
            float ssq8 = fmaf(r0q8, r0q8, r1q8 * r1q8);

#pragma unroll
            for (int off = 1; off < 4; off <<= 1) {
                siq  += __shfl_xor_sync(0xffffffffu, siq,  off);
                ssq  += __shfl_xor_sync(0xffffffffu, ssq,  off);
                siq8 += __shfl_xor_sync(0xffffffffu, siq8, off);
                ssq8 += __shfl_xor_sync(0xffffffffu, ssq8, off);
            }

            llv[iq] = 0.0f; llv[iq8] = 0.0f;
            imgv[iq] = -1;  imgv[iq8] = -1;
            if (tig == 0) {
                __stcs(out + r[iq],  siq  * 0.125f);
                __stcs(out + r[iq8], siq8 * 0.125f);
                llv[iq]  = fmaf(-0.5f, ssq,  -8.0f * (__logf(sg[iq])  + 0.5f * LOG_2PI_F));
                llv[iq8] = fmaf(-0.5f, ssq8, -8.0f * (__logf(sg[iq8]) + 0.5f * LOG_2PI_F));
                imgv[iq]  = img[iq];
                imgv[iq8] = img[iq8];
            }
        }

        // ======== PHASE 3: image aggregation, one call per reflection slot =====
        seg_atomic(llv[0], imgv[0], lane);
        seg_atomic(llv[1], imgv[1], lane);
        seg_atomic(llv[2], imgv[2], lane);
        seg_atomic(llv[3], imgv[3], lane);
    }
}

// ---------------- kernel 3: parallel finalize (8 blocks, last writes scalars) ---
__global__ __launch_bounds__(1024) void finalize_kernel(float* __restrict__ out) {
    int i = blockIdx.x * 1024 + threadIdx.x;
    float v = g_img_sum[i] * (1.0f / fmaxf(g_img_cnt[i], 1.0f));
#pragma unroll
    for (int off = 16; off; off >>= 1)
        v += __shfl_down_sync(0xffffffffu, v, off);
    __shared__ float wsum[32];
    int lane = threadIdx.x & 31, wid = threadIdx.x >> 5;
    if (lane == 0) wsum[wid] = v;
    __syncthreads();
    if (wid == 0) {
        float t = wsum[lane];
#pragma unroll
        for (int off = 16; off; off >>= 1)
            t += __shfl_down_sync(0xffffffffu, t, off);
        if (lane == 0) {
            atomicAdd(&g_ll_total, t);
            __threadfence();
            unsigned ticket = atomicAdd(&g_done, 1u);
            if (ticket == gridDim.x - 1) {
                float total = atomicAdd(&g_ll_total, 0.0f);
                out[N_REFLNS]     = -(total / (float)MC) / (float)N_IMAGES;
                out[N_REFLNS + 1] = g_kl_sum * (1.0f / (float)N_RAC);
            }
        }
    }
}

// ---------------- launch ----------------
extern "C" void kernel_launch(void* const* d_in, const int* in_sizes, int n_in,
                              void* d_out, int out_size) {
    const float* q_loc     = (const float*)d_in[0];
    const float* q_ls      = (const float*)d_in[1];
    const float* eps       = (const float*)d_in[2];
    const float* metadata  = (const float*)d_in[3];
    const float* W1        = (const float*)d_in[4];
    const float* b1        = (const float*)d_in[5];
    const float* W2        = (const float*)d_in[6];
    const float* b2        = (const float*)d_in[7];
    const float* iobs      = (const float*)d_in[8];
    const float* sigiobs   = (const float*)d_in[9];
    const int*   image_id  = (const int*)d_in[10];
    const int*   miller_id = (const int*)d_in[11];
    float* out = (float*)d_out;

    zkl_kernel<<<(N_RAC + 255) / 256, 256>>>(q_loc, q_ls, eps);
    refl_kernel<<<2368, 128>>>(metadata, W1, b1, W2, b2,
                               iobs, sigiobs, image_id, miller_id, out);
    finalize_kernel<<<N_IMAGES / 1024, 1024>>>(out);
}